// round 13
// baseline (speedup 1.0000x reference)
#include <cuda_runtime.h>
#include <cuda_fp16.h>
#include <cstdint>

// Problem constants
#define BATCH 4
#define SEQ   4096
#define DIM   1024
#define BT    (BATCH * SEQ)      // 16384

// GEMM tile config (fp16 operands, f32 accum)
// CTA tile 128x128, 4 warps, warp tile 64x64, BK=32.
// BARRIER-FREE private-FIFO pipeline: each thread cp.asyncs exactly the 16
// fragment chunks (8 A + 8 B, 16B each) it will consume into its own 256B smem
// region; visibility needs only cp.async.wait_group (issuing thread), so the
// mainloop has no __syncthreads at all. 3 stages x 32KB = 96KB dyn smem.
#define BM 128
#define BN 128
#define BK 32
#define NST 3
#define STAGE_BYTES (128 * 16 * 16)        // 128 threads * 16 chunks * 16B = 32KB
#define SMEM_DYN (NST * STAGE_BYTES)       // 96 KB

// Epilogue modes
#define EPI_EXP   3   // exp -> fp16 out + deterministic partial row sums
#define EPI_NORM  4   // f32 out scaled by per-row inv sum
#define EPI_QKV   5   // fused QKV projection: z selects W + destination (z==2 transposed)

// Scratch (allocation-free rule: __device__ globals)
__device__ __half g_X [(long long)BT*DIM];
__device__ __half g_Wq[(long long)DIM*DIM];
__device__ __half g_Wk[(long long)DIM*DIM];
__device__ __half g_Wv[(long long)DIM*DIM];
__device__ __half g_Q [(long long)BT*DIM];
__device__ __half g_K [(long long)BT*DIM];
__device__ __half g_Vt[(long long)BT*DIM];         // [e][b*SEQ + t], ld = BT
__device__ __half g_P [(long long)BATCH*SEQ*SEQ];  // unnormalized exp probs, fp16
__device__ float  g_psum[64LL * BT];               // partial row sums [slot][row]
__device__ float  g_inv [BT];                      // 1 / row sum

// cp.async with L1 caching (.ca): duplicate fragment fetches from paired warps
// merge in L1/MSHR, keeping L2 traffic near 1x.
__device__ __forceinline__ void cp16u(uint32_t saddr, const void* gm) {
    asm volatile("cp.async.ca.shared.global [%0], [%1], 16;" :: "r"(saddr), "l"(gm));
}

#define LDS128(v, addr)                                                      \
    asm volatile("ld.shared.v4.b32 {%0,%1,%2,%3}, [%4];"                     \
        : "=r"((v).x), "=r"((v).y), "=r"((v).z), "=r"((v).w) : "r"(addr))

#define MMA_F16(acc, a0, a1, a2, a3, b0, b1)                                \
    asm volatile(                                                           \
        "mma.sync.aligned.m16n8k16.row.col.f32.f16.f16.f32 "                \
        "{%0,%1,%2,%3}, {%4,%5,%6,%7}, {%8,%9}, {%0,%1,%2,%3};"             \
        : "+f"((acc)[0]), "+f"((acc)[1]), "+f"((acc)[2]), "+f"((acc)[3])    \
        : "r"(a0), "r"(a1), "r"(a2), "r"(a3), "r"(b0), "r"(b1))

// f32 -> f16 conversion, 4 elems/thread (x input)
__global__ void to_half_kernel(const float* __restrict__ in, __half* __restrict__ out,
                               long long n) {
    long long i = ((long long)blockIdx.x * blockDim.x + threadIdx.x) * 4;
    if (i < n) {
        float4 v = *(const float4*)(in + i);
        __half2 h0 = __floats2half2_rn(v.x, v.y);
        __half2 h1 = __floats2half2_rn(v.z, v.w);
        *(uint2*)(out + i) = make_uint2(*(uint32_t*)&h0, *(uint32_t*)&h1);
    }
}

// All three weight converts in one launch: 1024 blocks per weight (1M elems each).
__global__ void w_to_half_kernel(const float* __restrict__ Wq,
                                 const float* __restrict__ Wk,
                                 const float* __restrict__ Wv) {
    int seg = blockIdx.x >> 10;
    const float* in = (seg == 0) ? Wq : (seg == 1) ? Wk : Wv;
    __half* out = (seg == 0) ? g_Wq : (seg == 1) ? g_Wk : g_Wv;
    long long i = (((long long)(blockIdx.x & 1023)) * 256 + threadIdx.x) * 4;
    float4 v = *(const float4*)(in + i);
    __half2 h0 = __floats2half2_rn(v.x, v.y);
    __half2 h1 = __floats2half2_rn(v.z, v.w);
    *(uint2*)(out + i) = make_uint2(*(uint32_t*)&h0, *(uint32_t*)&h1);
}

// Sum 64 partials per row, store reciprocal. grid = BT/256, block 256.
__global__ void rowinv_kernel(const float* __restrict__ psum, float* __restrict__ inv) {
    int row = blockIdx.x * 256 + threadIdx.x;
    float s = 0.f;
    #pragma unroll
    for (int j = 0; j < 64; j++) s += psum[(long long)j * BT + row];
    inv[row] = 1.f / s;
}

// C[M,N] = alpha * A[M,K] * B[N,K]^T, fp16 operands (K-contiguous), f32 accumulate.
// Fragment semantics identical to previous rounds (k-permutation trick): thread
// (g,tg) holds k = {8tg..8tg+7} per 16B chunk; mma step0 uses halves 0..3,
// step1 halves 4..7; A/B thread-slot assignments agree, so dot products are exact.
//
// Private FIFO layout: stage s at s*32KB; chunk c (0..15) at c*2048; thread at
// tid*16. Chunks 0..7 = A (mt*2+h: row wm*64+mt*16+h*8+g), 8..15 = B (nt: row
// wn*64+nt*8+g). Lane stride 16B -> conflict-free LDS.128 / coalesced writes.
template<int EPI>
__global__ void __launch_bounds__(128, 2) gemm_f16(
    const __half* __restrict__ A, const __half* __restrict__ B, void* __restrict__ Cv,
    float* __restrict__ aux,   // EPI_EXP: psum base; EPI_NORM: inv base
    int lda, int ldb, int ldc,
    long long sA, long long sB, long long sC,
    int K, float alpha)
{
    extern __shared__ char dsm[];

    const __half* Bsel = B;
    if (EPI == EPI_QKV)
        Bsel = (blockIdx.z == 0) ? g_Wq : (blockIdx.z == 1) ? g_Wk : g_Wv;

    const __half* Ab = A + (long long)blockIdx.z * sA + (long long)blockIdx.y * BM * lda;
    const __half* Bb = Bsel + ((EPI == EPI_QKV) ? 0 : (long long)blockIdx.z * sB)
                            + (long long)blockIdx.x * BN * ldb;

    const int tid  = threadIdx.x;
    const int lane = tid & 31;
    const int warp = tid >> 5;      // 0..3
    const int wm = warp >> 1;       // 0..1
    const int wn = warp & 1;        // 0..1
    const int g  = lane >> 2;       // 0..7
    const int tg = lane & 3;        // 0..3

    // Thread's base in the private FIFO
    uint32_t sbase;
    asm("{ .reg .u64 t; cvta.to.shared.u64 t, %1; cvt.u32.u64 %0, t; }"
        : "=r"(sbase) : "l"(dsm));
    sbase += tid * 16;

    // Per-thread global fragment base pointers (k-position tg*8 within stage)
    const __half* aptr = Ab + (long long)(wm * 64 + g) * lda + tg * 8;
    const __half* bptr = Bb + (long long)(wn * 64 + g) * ldb + tg * 8;

    float acc[4][8][4];
    #pragma unroll
    for (int i = 0; i < 4; i++)
        #pragma unroll
        for (int j = 0; j < 8; j++)
            #pragma unroll
            for (int c = 0; c < 4; c++) acc[i][j][c] = 0.f;

    const int KT = K / BK;   // 32 or 128

    // Load this thread's 16 fragment chunks for one stage; one commit group.
    auto load = [&](const __half* ga, const __half* gb, uint32_t st, bool pred) {
        if (pred) {
            #pragma unroll
            for (int mt = 0; mt < 4; mt++) {
                cp16u(sbase + st + (mt * 2    ) * 2048,
                      ga + (long long)(mt * 16    ) * lda);
                cp16u(sbase + st + (mt * 2 + 1) * 2048,
                      ga + (long long)(mt * 16 + 8) * lda);
            }
            #pragma unroll
            for (int nt = 0; nt < 8; nt++)
                cp16u(sbase + st + (8 + nt) * 2048,
                      gb + (long long)(nt * 8) * ldb);
        }
        asm volatile("cp.async.commit_group;");
    };

    // Prologue: stages 0,1
    uint32_t st0 = 0, st1 = STAGE_BYTES, st2 = 2 * STAGE_BYTES;
    load(aptr, bptr, st0, true); aptr += BK; bptr += BK;
    load(aptr, bptr, st1, true); aptr += BK; bptr += BK;

    for (int kt = 0; kt < KT; kt++) {
        // Own groups: stages kt, kt+1 pending -> wait until <=1 pending =>
        // stage kt's data is in this thread's smem region. No barrier needed.
        asm volatile("cp.async.wait_group 1;");

        uint4 a[4][2], b[8];
        #pragma unroll
        for (int mt = 0; mt < 4; mt++) {
            LDS128(a[mt][0], sbase + st0 + (mt * 2    ) * 2048);
            LDS128(a[mt][1], sbase + st0 + (mt * 2 + 1) * 2048);
        }
        #pragma unroll
        for (int nt = 0; nt < 8; nt++)
            LDS128(b[nt], sbase + st0 + (8 + nt) * 2048);

        // Refill slot st2 (held stage kt-1; this thread consumed it last iter).
        load(aptr, bptr, st2, kt + 2 < KT);
        aptr += BK; bptr += BK;

        #pragma unroll
        for (int mt = 0; mt < 4; mt++) {
            #pragma unroll
            for (int nt = 0; nt < 8; nt++)
                MMA_F16(acc[mt][nt], a[mt][0].x, a[mt][1].x, a[mt][0].y, a[mt][1].y,
                        b[nt].x, b[nt].y);
            #pragma unroll
            for (int nt = 0; nt < 8; nt++)
                MMA_F16(acc[mt][nt], a[mt][0].z, a[mt][1].z, a[mt][0].w, a[mt][1].w,
                        b[nt].z, b[nt].w);
        }

        // Rotate stage slots
        uint32_t t = st0; st0 = st1; st1 = st2; st2 = t;
    }

    // ---------------- Epilogue ----------------
    const int zq = (EPI == EPI_QKV) ? (int)blockIdx.z : 0;
    __half* Cq = nullptr;
    int ldq = ldc;
    if (EPI == EPI_QKV) {
        Cq = (zq == 0) ? g_Q : (zq == 1) ? g_K : g_Vt;
        ldq = (zq == 2) ? BT : DIM;
    }

    #pragma unroll
    for (int mt = 0; mt < 4; mt++) {
        int row0 = blockIdx.y * BM + wm * 64 + mt * 16 + g;   // within batch matrix
        float plo = 0.f, phi = 0.f;                            // EPI_EXP row partials
        float inv0 = 1.f, inv1 = 1.f;
        if (EPI == EPI_NORM) {
            const float* invp = aux + (long long)blockIdx.z * SEQ;
            inv0 = __ldg(&invp[row0]);
            inv1 = __ldg(&invp[row0 + 8]);
        }
        #pragma unroll
        for (int nt = 0; nt < 8; nt++) {
            int col0 = blockIdx.x * BN + wn * 64 + nt * 8 + 2 * tg;
            float v0 = acc[mt][nt][0] * alpha;
            float v1 = acc[mt][nt][1] * alpha;
            float v2 = acc[mt][nt][2] * alpha;
            float v3 = acc[mt][nt][3] * alpha;

            if (EPI == EPI_QKV) {
                if (zq < 2) {
                    __half2 h01 = __floats2half2_rn(v0, v1);
                    __half2 h23 = __floats2half2_rn(v2, v3);
                    *(__half2*)&Cq[(long long)(row0    ) * ldq + col0] = h01;
                    *(__half2*)&Cq[(long long)(row0 + 8) * ldq + col0] = h23;
                } else {
                    Cq[(long long)(col0    ) * ldq + row0    ] = __float2half_rn(v0);
                    Cq[(long long)(col0 + 1) * ldq + row0    ] = __float2half_rn(v1);
                    Cq[(long long)(col0    ) * ldq + row0 + 8] = __float2half_rn(v2);
                    Cq[(long long)(col0 + 1) * ldq + row0 + 8] = __float2half_rn(v3);
                }
            } else if (EPI == EPI_EXP) {
                __half* C = (__half*)Cv + (long long)blockIdx.z * sC;
                float e0 = __expf(fminf(v0, 11.f));
                float e1 = __expf(fminf(v1, 11.f));
                float e2 = __expf(fminf(v2, 11.f));
                float e3 = __expf(fminf(v3, 11.f));
                plo += e0 + e1; phi += e2 + e3;
                __half2 h01 = __floats2half2_rn(e0, e1);
                __half2 h23 = __floats2half2_rn(e2, e3);
                *(__half2*)&C[(long long)(row0    ) * ldc + col0] = h01;
                *(__half2*)&C[(long long)(row0 + 8) * ldc + col0] = h23;
            } else { // EPI_NORM
                float* C = (float*)Cv + (long long)blockIdx.z * sC;
                *(float2*)&C[(long long)(row0    ) * ldc + col0] =
                    make_float2(v0 * inv0, v1 * inv0);
                *(float2*)&C[(long long)(row0 + 8) * ldc + col0] =
                    make_float2(v2 * inv1, v3 * inv1);
            }
        }
        if (EPI == EPI_EXP) {
            // quad reduce across tg (lane bits 0,1), then leader stores partials.
            plo += __shfl_xor_sync(0xffffffffu, plo, 1);
            plo += __shfl_xor_sync(0xffffffffu, plo, 2);
            phi += __shfl_xor_sync(0xffffffffu, phi, 1);
            phi += __shfl_xor_sync(0xffffffffu, phi, 2);
            if (tg == 0) {
                long long slot = (long long)(blockIdx.x * 2 + wn) * BT
                               + (long long)blockIdx.z * SEQ;
                aux[slot + row0    ] = plo;
                aux[slot + row0 + 8] = phi;
            }
        }
    }
}

extern "C" void kernel_launch(void* const* d_in, const int* in_sizes, int n_in,
                              void* d_out, int out_size) {
    const float* x  = (const float*)d_in[0];
    const float* Wq = (const float*)d_in[1];
    const float* Wk = (const float*)d_in[2];
    const float* Wv = (const float*)d_in[3];
    float* out = (float*)d_out;

    __half *pX, *pQ, *pK, *pVt, *pP;
    float *pPsum, *pInv;
    cudaGetSymbolAddress((void**)&pX,  g_X);
    cudaGetSymbolAddress((void**)&pQ,  g_Q);
    cudaGetSymbolAddress((void**)&pK,  g_K);
    cudaGetSymbolAddress((void**)&pVt, g_Vt);
    cudaGetSymbolAddress((void**)&pP,  g_P);
    cudaGetSymbolAddress((void**)&pPsum, g_psum);
    cudaGetSymbolAddress((void**)&pInv,  g_inv);

    cudaFuncSetAttribute(gemm_f16<EPI_QKV >, cudaFuncAttributeMaxDynamicSharedMemorySize, SMEM_DYN);
    cudaFuncSetAttribute(gemm_f16<EPI_EXP >, cudaFuncAttributeMaxDynamicSharedMemorySize, SMEM_DYN);
    cudaFuncSetAttribute(gemm_f16<EPI_NORM>, cudaFuncAttributeMaxDynamicSharedMemorySize, SMEM_DYN);

    const long long nX = (long long)BT * DIM;
    const long long strideQK = (long long)SEQ * DIM;
    const long long strideS  = (long long)SEQ * SEQ;

    // Convert inputs to fp16 (x + all three weights in 2 launches)
    to_half_kernel<<<(unsigned)(nX / 4 / 256), 256>>>(x, pX, nX);
    w_to_half_kernel<<<3 * 1024, 256>>>(Wq, Wk, Wv);

    // Fused QKV projections: one launch, z selects weight + destination.
    dim3 gProj(DIM / BN, BT / BM, 3);
    gemm_f16<EPI_QKV><<<gProj, 128, SMEM_DYN>>>(pX, nullptr, nullptr, nullptr,
                                                DIM, DIM, DIM, 0, 0, 0, DIM, 1.0f);

    // Scores + exp fused: P_b = exp(Q_b K_b^T / 32), partial row sums to psum
    dim3 gS(SEQ / BN, SEQ / BM, BATCH);
    gemm_f16<EPI_EXP><<<gS, 128, SMEM_DYN>>>(pQ, pK, pP, pPsum, DIM, DIM, SEQ,
                                             strideQK, strideQK, strideS, DIM, 0.03125f);

    // Row sums -> reciprocals
    rowinv_kernel<<<BT / 256, 256>>>(pPsum, pInv);

    // Output: O_b = (P_b V_b) * inv_rowsum -> f32
    dim3 gO(DIM / BN, SEQ / BM, BATCH);
    gemm_f16<EPI_NORM><<<gO, 128, SMEM_DYN>>>(pP, pVt, out, pInv, SEQ, BT, DIM,
                                              strideS, (long long)SEQ, (long long)SEQ * DIM,
                                              SEQ, 1.0f);
}

// round 15
// speedup vs baseline: 1.2855x; 1.2855x over previous
#include <cuda_runtime.h>
#include <cuda_fp16.h>
#include <cstdint>

// Problem constants
#define BATCH 4
#define SEQ   4096
#define DIM   1024
#define BT    (BATCH * SEQ)      // 16384

// GEMM tile config (fp16 operands, f32 accum)
// CTA tile 128x128, 4 warps, warp tile 64x64, BK=32.
// 7-slot cp.async pipeline, ONE wait_group+__syncthreads per PAIR of
// k-iterations. Writes target only slots whose reads finished before the
// current barrier (stages kt-2 / kt-1), making the barrier-free odd
// iteration race-free for all warps.
#define BM 128
#define BN 128
#define BK 32
#define NST 7
#define ASTAGE (BM * BK)                       // halves per A stage (8KB)
#define BSTAGE (BN * BK)
#define SMEM_DYN (NST * (ASTAGE + BSTAGE) * 2) // 112 KB

// Epilogue modes
#define EPI_EXP   3   // exp -> fp16 out + deterministic partial row sums
#define EPI_NORM  4   // f32 out scaled by per-row inv sum
#define EPI_QKV   5   // fused QKV projection: z selects W + destination (z==2 transposed)

// Scratch (allocation-free rule: __device__ globals)
__device__ __half g_X [(long long)BT*DIM];
__device__ __half g_Wq[(long long)DIM*DIM];
__device__ __half g_Wk[(long long)DIM*DIM];
__device__ __half g_Wv[(long long)DIM*DIM];
__device__ __half g_Q [(long long)BT*DIM];
__device__ __half g_K [(long long)BT*DIM];
__device__ __half g_Vt[(long long)BT*DIM];         // [e][b*SEQ + t], ld = BT
__device__ __half g_P [(long long)BATCH*SEQ*SEQ];  // unnormalized exp probs, fp16
__device__ float  g_psum[64LL * BT];               // partial row sums [slot][row]
__device__ float  g_inv [BT];                      // 1 / row sum

__device__ __forceinline__ void cp16s(void* sm, const void* gm) {
    unsigned s = (unsigned)__cvta_generic_to_shared(sm);
    asm volatile("cp.async.cg.shared.global [%0], [%1], 16;" :: "r"(s), "l"(gm));
}

#define MMA_F16(acc, a0, a1, a2, a3, b0, b1)                                \
    asm volatile(                                                           \
        "mma.sync.aligned.m16n8k16.row.col.f32.f16.f16.f32 "                \
        "{%0,%1,%2,%3}, {%4,%5,%6,%7}, {%8,%9}, {%0,%1,%2,%3};"             \
        : "+f"((acc)[0]), "+f"((acc)[1]), "+f"((acc)[2]), "+f"((acc)[3])    \
        : "r"(a0), "r"(a1), "r"(a2), "r"(a3), "r"(b0), "r"(b1))

// f32 -> f16 conversion, 4 elems/thread (x input)
__global__ void to_half_kernel(const float* __restrict__ in, __half* __restrict__ out,
                               long long n) {
    long long i = ((long long)blockIdx.x * blockDim.x + threadIdx.x) * 4;
    if (i < n) {
        float4 v = *(const float4*)(in + i);
        __half2 h0 = __floats2half2_rn(v.x, v.y);
        __half2 h1 = __floats2half2_rn(v.z, v.w);
        *(uint2*)(out + i) = make_uint2(*(uint32_t*)&h0, *(uint32_t*)&h1);
    }
}

// All three weight converts in one launch: 1024 blocks per weight (1M elems each).
__global__ void w_to_half_kernel(const float* __restrict__ Wq,
                                 const float* __restrict__ Wk,
                                 const float* __restrict__ Wv) {
    int seg = blockIdx.x >> 10;
    const float* in = (seg == 0) ? Wq : (seg == 1) ? Wk : Wv;
    __half* out = (seg == 0) ? g_Wq : (seg == 1) ? g_Wk : g_Wv;
    long long i = (((long long)(blockIdx.x & 1023)) * 256 + threadIdx.x) * 4;
    float4 v = *(const float4*)(in + i);
    __half2 h0 = __floats2half2_rn(v.x, v.y);
    __half2 h1 = __floats2half2_rn(v.z, v.w);
    *(uint2*)(out + i) = make_uint2(*(uint32_t*)&h0, *(uint32_t*)&h1);
}

// Sum 64 partials per row, store reciprocal. grid = BT/256, block 256.
__global__ void rowinv_kernel(const float* __restrict__ psum, float* __restrict__ inv) {
    int row = blockIdx.x * 256 + threadIdx.x;
    float s = 0.f;
    #pragma unroll
    for (int j = 0; j < 64; j++) s += psum[(long long)j * BT + row];
    inv[row] = 1.f / s;
}

// C[M,N] = alpha * A[M,K] * B[N,K]^T, fp16 operands (K-contiguous), f32 accumulate.
// k-permutation trick: one LDS.128 per row gives thread tg k = {8tg..8tg+7};
// mma step0 uses {8tg..8tg+3}, step1 uses {8tg+4..8tg+7}; A/B slots agree.
template<int EPI>
__global__ void __launch_bounds__(128, 2) gemm_f16(
    const __half* __restrict__ A, const __half* __restrict__ B, void* __restrict__ Cv,
    float* __restrict__ aux,   // EPI_EXP: psum base; EPI_NORM: inv base
    int lda, int ldb, int ldc,
    long long sA, long long sB, long long sC,
    int K, float alpha)
{
    extern __shared__ __half dsm[];

    const __half* Bsel = B;
    if (EPI == EPI_QKV)
        Bsel = (blockIdx.z == 0) ? g_Wq : (blockIdx.z == 1) ? g_Wk : g_Wv;

    const __half* Ab = A + (long long)blockIdx.z * sA + (long long)blockIdx.y * BM * lda;
    const __half* Bb = Bsel + ((EPI == EPI_QKV) ? 0 : (long long)blockIdx.z * sB)
                            + (long long)blockIdx.x * BN * ldb;

    const int tid  = threadIdx.x;
    const int lane = tid & 31;
    const int warp = tid >> 5;      // 0..3
    const int wm = warp >> 1;       // 0..1
    const int wn = warp & 1;        // 0..1
    const int g  = lane >> 2;       // 0..7
    const int tg = lane & 3;        // 0..3

    // Slot map at start of pair kt: p0..p4 -> stages kt..kt+4,
    // p5 -> slot(kt-2), p6 -> slot(kt-1) (reads finished before this pair's
    // barrier; safe overwrite targets for stages kt+5 / kt+6).
    __half* pa[NST];
    __half* pb[NST];
    #pragma unroll
    for (int s = 0; s < NST; s++) {
        pa[s] = dsm + s * ASTAGE;
        pb[s] = dsm + NST * ASTAGE + s * BSTAGE;
    }

    // Loader: row = (tid>>2) + 32*i (i=0..3), 16B chunk = (tid&3)*8 halves
    const int lr  = tid >> 2;
    const int lc8 = (tid & 3) * 8;
    const __half* aptr = Ab + (long long)lr * lda + lc8;
    const __half* bptr = Bb + (long long)lr * ldb + lc8;

    float acc[4][8][4];
    #pragma unroll
    for (int i = 0; i < 4; i++)
        #pragma unroll
        for (int j = 0; j < 8; j++)
            #pragma unroll
            for (int c = 0; c < 4; c++) acc[i][j][c] = 0.f;

    const int KT = K / BK;   // 32 or 128 — even

    auto load = [&](__half* sa, __half* sb, bool pred) {
        if (pred) {
            #pragma unroll
            for (int i = 0; i < 4; i++)
                cp16s(&sa[(lr + i * 32) * BK + lc8], aptr + (long long)(i * 32) * lda);
            #pragma unroll
            for (int i = 0; i < 4; i++)
                cp16s(&sb[(lr + i * 32) * BK + lc8], bptr + (long long)(i * 32) * ldb);
        }
        asm volatile("cp.async.commit_group;");
        aptr += BK;
        bptr += BK;
    };

    // Rotate left by 2 (one pair): new p0..p4 = old p2..p6; p5,p6 = old p0,p1.
    auto rotate2 = [&]() {
        __half* t0a = pa[0]; __half* t1a = pa[1];
        __half* t0b = pb[0]; __half* t1b = pb[1];
        #pragma unroll
        for (int s = 0; s < NST - 2; s++) { pa[s] = pa[s + 2]; pb[s] = pb[s + 2]; }
        pa[NST - 2] = t0a; pa[NST - 1] = t1a;
        pb[NST - 2] = t0b; pb[NST - 1] = t1b;
    };

    uint4 bb_cur[8], bb_nxt[8];
    auto mma_iter = [&](const __half* as, const __half* bsn, bool PREF) {
        #pragma unroll
        for (int mt = 0; mt < 4; mt++) {
            int r0 = wm * 64 + mt * 16;
            uint4 alo = *(const uint4*)&as[(r0 + g    ) * BK + tg * 8];
            uint4 ahi = *(const uint4*)&as[(r0 + g + 8) * BK + tg * 8];
            #pragma unroll
            for (int nt = 0; nt < 8; nt++)
                MMA_F16(acc[mt][nt], alo.x, ahi.x, alo.y, ahi.y,
                        bb_cur[nt].x, bb_cur[nt].y);
            if (PREF && mt == 0) {
                #pragma unroll
                for (int nt = 0; nt < 8; nt++)
                    bb_nxt[nt] =
                        *(const uint4*)&bsn[(wn * 64 + nt * 8 + g) * BK + tg * 8];
            }
            #pragma unroll
            for (int nt = 0; nt < 8; nt++)
                MMA_F16(acc[mt][nt], alo.z, ahi.z, alo.w, ahi.w,
                        bb_cur[nt].z, bb_cur[nt].w);
        }
    };

    // Prologue: stages 0..4 into p0..p4 (5 groups)
    #pragma unroll
    for (int s = 0; s < 5; s++) load(pa[s], pb[s], true);

    for (int kt = 0; kt < KT; kt += 2) {
        // Issued groups cover stages <= kt+4; wait_group 3 => stages <= kt+1
        // complete; barrier publishes BOTH to all threads. All reads of stages
        // kt-2 / kt-1 (this pair's write targets) finished before this barrier.
        asm volatile("cp.async.wait_group 3;");
        __syncthreads();

        // ---- even iteration kt ----
        #pragma unroll
        for (int nt = 0; nt < 8; nt++)
            bb_cur[nt] = *(const uint4*)&pb[0][(wn * 64 + nt * 8 + g) * BK + tg * 8];

        load(pa[5], pb[5], kt + 5 < KT);   // stage kt+5 -> slot(kt-2)

        mma_iter(pa[0], pb[1], true);      // prefetch bb_nxt from stage kt+1
        #pragma unroll
        for (int nt = 0; nt < 8; nt++) bb_cur[nt] = bb_nxt[nt];

        // ---- odd iteration kt+1: NO wait, NO barrier ----
        load(pa[6], pb[6], kt + 6 < KT);   // stage kt+6 -> slot(kt-1)

        mma_iter(pa[1], nullptr, false);   // stage kt+1 (published above)

        rotate2();
    }

    // ---------------- Epilogue ----------------
    const int zq = (EPI == EPI_QKV) ? (int)blockIdx.z : 0;
    __half* Cq = nullptr;
    int ldq = ldc;
    if (EPI == EPI_QKV) {
        Cq = (zq == 0) ? g_Q : (zq == 1) ? g_K : g_Vt;
        ldq = (zq == 2) ? BT : DIM;
    }

    #pragma unroll
    for (int mt = 0; mt < 4; mt++) {
        int row0 = blockIdx.y * BM + wm * 64 + mt * 16 + g;   // within batch matrix
        float plo = 0.f, phi = 0.f;                            // EPI_EXP row partials
        float inv0 = 1.f, inv1 = 1.f;
        if (EPI == EPI_NORM) {
            const float* invp = aux + (long long)blockIdx.z * SEQ;
            inv0 = __ldg(&invp[row0]);
            inv1 = __ldg(&invp[row0 + 8]);
        }
        #pragma unroll
        for (int nt = 0; nt < 8; nt++) {
            int col0 = blockIdx.x * BN + wn * 64 + nt * 8 + 2 * tg;
            float v0 = acc[mt][nt][0] * alpha;
            float v1 = acc[mt][nt][1] * alpha;
            float v2 = acc[mt][nt][2] * alpha;
            float v3 = acc[mt][nt][3] * alpha;

            if (EPI == EPI_QKV) {
                if (zq < 2) {
                    __half2 h01 = __floats2half2_rn(v0, v1);
                    __half2 h23 = __floats2half2_rn(v2, v3);
                    *(__half2*)&Cq[(long long)(row0    ) * ldq + col0] = h01;
                    *(__half2*)&Cq[(long long)(row0 + 8) * ldq + col0] = h23;
                } else {
                    Cq[(long long)(col0    ) * ldq + row0    ] = __float2half_rn(v0);
                    Cq[(long long)(col0 + 1) * ldq + row0    ] = __float2half_rn(v1);
                    Cq[(long long)(col0    ) * ldq + row0 + 8] = __float2half_rn(v2);
                    Cq[(long long)(col0 + 1) * ldq + row0 + 8] = __float2half_rn(v3);
                }
            } else if (EPI == EPI_EXP) {
                __half* C = (__half*)Cv + (long long)blockIdx.z * sC;
                float e0 = __expf(fminf(v0, 11.f));
                float e1 = __expf(fminf(v1, 11.f));
                float e2 = __expf(fminf(v2, 11.f));
                float e3 = __expf(fminf(v3, 11.f));
                plo += e0 + e1; phi += e2 + e3;
                __half2 h01 = __floats2half2_rn(e0, e1);
                __half2 h23 = __floats2half2_rn(e2, e3);
                *(__half2*)&C[(long long)(row0    ) * ldc + col0] = h01;
                *(__half2*)&C[(long long)(row0 + 8) * ldc + col0] = h23;
            } else { // EPI_NORM
                float* C = (float*)Cv + (long long)blockIdx.z * sC;
                *(float2*)&C[(long long)(row0    ) * ldc + col0] =
                    make_float2(v0 * inv0, v1 * inv0);
                *(float2*)&C[(long long)(row0 + 8) * ldc + col0] =
                    make_float2(v2 * inv1, v3 * inv1);
            }
        }
        if (EPI == EPI_EXP) {
            // quad reduce across tg (lane bits 0,1), then leader stores partials.
            plo += __shfl_xor_sync(0xffffffffu, plo, 1);
            plo += __shfl_xor_sync(0xffffffffu, plo, 2);
            phi += __shfl_xor_sync(0xffffffffu, phi, 1);
            phi += __shfl_xor_sync(0xffffffffu, phi, 2);
            if (tg == 0) {
                long long slot = (long long)(blockIdx.x * 2 + wn) * BT
                               + (long long)blockIdx.z * SEQ;
                aux[slot + row0    ] = plo;
                aux[slot + row0 + 8] = phi;
            }
        }
    }
}

extern "C" void kernel_launch(void* const* d_in, const int* in_sizes, int n_in,
                              void* d_out, int out_size) {
    const float* x  = (const float*)d_in[0];
    const float* Wq = (const float*)d_in[1];
    const float* Wk = (const float*)d_in[2];
    const float* Wv = (const float*)d_in[3];
    float* out = (float*)d_out;

    __half *pX, *pQ, *pK, *pVt, *pP;
    float *pPsum, *pInv;
    cudaGetSymbolAddress((void**)&pX,  g_X);
    cudaGetSymbolAddress((void**)&pQ,  g_Q);
    cudaGetSymbolAddress((void**)&pK,  g_K);
    cudaGetSymbolAddress((void**)&pVt, g_Vt);
    cudaGetSymbolAddress((void**)&pP,  g_P);
    cudaGetSymbolAddress((void**)&pPsum, g_psum);
    cudaGetSymbolAddress((void**)&pInv,  g_inv);

    cudaFuncSetAttribute(gemm_f16<EPI_QKV >, cudaFuncAttributeMaxDynamicSharedMemorySize, SMEM_DYN);
    cudaFuncSetAttribute(gemm_f16<EPI_EXP >, cudaFuncAttributeMaxDynamicSharedMemorySize, SMEM_DYN);
    cudaFuncSetAttribute(gemm_f16<EPI_NORM>, cudaFuncAttributeMaxDynamicSharedMemorySize, SMEM_DYN);

    const long long nX = (long long)BT * DIM;
    const long long strideQK = (long long)SEQ * DIM;
    const long long strideS  = (long long)SEQ * SEQ;

    // Convert inputs to fp16 (x + all three weights in 2 launches)
    to_half_kernel<<<(unsigned)(nX / 4 / 256), 256>>>(x, pX, nX);
    w_to_half_kernel<<<3 * 1024, 256>>>(Wq, Wk, Wv);

    // Fused QKV projections: one launch, z selects weight + destination.
    dim3 gProj(DIM / BN, BT / BM, 3);
    gemm_f16<EPI_QKV><<<gProj, 128, SMEM_DYN>>>(pX, nullptr, nullptr, nullptr,
                                                DIM, DIM, DIM, 0, 0, 0, DIM, 1.0f);

    // Scores + exp fused: P_b = exp(Q_b K_b^T / 32), partial row sums to psum
    dim3 gS(SEQ / BN, SEQ / BM, BATCH);
    gemm_f16<EPI_EXP><<<gS, 128, SMEM_DYN>>>(pQ, pK, pP, pPsum, DIM, DIM, SEQ,
                                             strideQK, strideQK, strideS, DIM, 0.03125f);

    // Row sums -> reciprocals
    rowinv_kernel<<<BT / 256, 256>>>(pPsum, pInv);

    // Output: O_b = (P_b V_b) * inv_rowsum -> f32
    dim3 gO(DIM / BN, SEQ / BM, BATCH);
    gemm_f16<EPI_NORM><<<gO, 128, SMEM_DYN>>>(pP, pVt, out, pInv, SEQ, BT, DIM,
                                              strideS, (long long)SEQ, (long long)SEQ * DIM,
                                              SEQ, 1.0f);
}

// round 16
// speedup vs baseline: 1.3055x; 1.0155x over previous
#include <cuda_runtime.h>
#include <cuda_fp16.h>
#include <cstdint>

// Problem constants
#define BATCH 4
#define SEQ   4096
#define DIM   1024
#define BT    (BATCH * SEQ)      // 16384

// GEMM tile config (fp16 operands, f32 accum)
// CTA tile 128x128, 4 warps, warp tile 64x64, BK=32, 5-slot cp.async pipeline
// (wait_group 2 => two loads in flight). Register double-buffering of the B
// fragments AND the mt=0 A fragments: the first MMA block after each barrier
// issues immediately from registers (no post-barrier LDS bubble).
#define BM 128
#define BN 128
#define BK 32
#define NST 5
#define ASTAGE (BM * BK)                       // halves per A stage (8KB)
#define BSTAGE (BN * BK)
#define SMEM_DYN (NST * (ASTAGE + BSTAGE) * 2) // 80 KB

// Epilogue modes
#define EPI_EXP   3   // exp -> fp16 out + deterministic partial row sums
#define EPI_NORM  4   // f32 out scaled by per-row inv sum
#define EPI_QKV   5   // fused QKV projection: z selects W + destination (z==2 transposed)

// Scratch (allocation-free rule: __device__ globals)
__device__ __half g_X [(long long)BT*DIM];
__device__ __half g_Wq[(long long)DIM*DIM];
__device__ __half g_Wk[(long long)DIM*DIM];
__device__ __half g_Wv[(long long)DIM*DIM];
__device__ __half g_Q [(long long)BT*DIM];
__device__ __half g_K [(long long)BT*DIM];
__device__ __half g_Vt[(long long)BT*DIM];         // [e][b*SEQ + t], ld = BT
__device__ __half g_P [(long long)BATCH*SEQ*SEQ];  // unnormalized exp probs, fp16
__device__ float  g_psum[64LL * BT];               // partial row sums [slot][row]
__device__ float  g_inv [BT];                      // 1 / row sum

__device__ __forceinline__ void cp16s(void* sm, const void* gm) {
    unsigned s = (unsigned)__cvta_generic_to_shared(sm);
    asm volatile("cp.async.cg.shared.global [%0], [%1], 16;" :: "r"(s), "l"(gm));
}

#define MMA_F16(acc, a0, a1, a2, a3, b0, b1)                                \
    asm volatile(                                                           \
        "mma.sync.aligned.m16n8k16.row.col.f32.f16.f16.f32 "                \
        "{%0,%1,%2,%3}, {%4,%5,%6,%7}, {%8,%9}, {%0,%1,%2,%3};"             \
        : "+f"((acc)[0]), "+f"((acc)[1]), "+f"((acc)[2]), "+f"((acc)[3])    \
        : "r"(a0), "r"(a1), "r"(a2), "r"(a3), "r"(b0), "r"(b1))

// f32 -> f16 conversion, 4 elems/thread (x input)
__global__ void to_half_kernel(const float* __restrict__ in, __half* __restrict__ out,
                               long long n) {
    long long i = ((long long)blockIdx.x * blockDim.x + threadIdx.x) * 4;
    if (i < n) {
        float4 v = *(const float4*)(in + i);
        __half2 h0 = __floats2half2_rn(v.x, v.y);
        __half2 h1 = __floats2half2_rn(v.z, v.w);
        *(uint2*)(out + i) = make_uint2(*(uint32_t*)&h0, *(uint32_t*)&h1);
    }
}

// All three weight converts in one launch: 1024 blocks per weight (1M elems each).
__global__ void w_to_half_kernel(const float* __restrict__ Wq,
                                 const float* __restrict__ Wk,
                                 const float* __restrict__ Wv) {
    int seg = blockIdx.x >> 10;
    const float* in = (seg == 0) ? Wq : (seg == 1) ? Wk : Wv;
    __half* out = (seg == 0) ? g_Wq : (seg == 1) ? g_Wk : g_Wv;
    long long i = (((long long)(blockIdx.x & 1023)) * 256 + threadIdx.x) * 4;
    float4 v = *(const float4*)(in + i);
    __half2 h0 = __floats2half2_rn(v.x, v.y);
    __half2 h1 = __floats2half2_rn(v.z, v.w);
    *(uint2*)(out + i) = make_uint2(*(uint32_t*)&h0, *(uint32_t*)&h1);
}

// Sum 64 partials per row, store reciprocal. grid = BT/256, block 256.
__global__ void rowinv_kernel(const float* __restrict__ psum, float* __restrict__ inv) {
    int row = blockIdx.x * 256 + threadIdx.x;
    float s = 0.f;
    #pragma unroll
    for (int j = 0; j < 64; j++) s += psum[(long long)j * BT + row];
    inv[row] = 1.f / s;
}

// C[M,N] = alpha * A[M,K] * B[N,K]^T, fp16 operands (K-contiguous), f32 accumulate.
// k-permutation trick: one LDS.128 per row gives thread tg k = {8tg..8tg+7};
// mma step0 uses {8tg..8tg+3}, step1 uses {8tg+4..8tg+7}; A/B slots agree.
template<int EPI>
__global__ void __launch_bounds__(128, 2) gemm_f16(
    const __half* __restrict__ A, const __half* __restrict__ B, void* __restrict__ Cv,
    float* __restrict__ aux,   // EPI_EXP: psum base; EPI_NORM: inv base
    int lda, int ldb, int ldc,
    long long sA, long long sB, long long sC,
    int K, float alpha)
{
    extern __shared__ __half dsm[];

    const __half* Bsel = B;
    if (EPI == EPI_QKV)
        Bsel = (blockIdx.z == 0) ? g_Wq : (blockIdx.z == 1) ? g_Wk : g_Wv;

    const __half* Ab = A + (long long)blockIdx.z * sA + (long long)blockIdx.y * BM * lda;
    const __half* Bb = Bsel + ((EPI == EPI_QKV) ? 0 : (long long)blockIdx.z * sB)
                            + (long long)blockIdx.x * BN * ldb;

    const int tid  = threadIdx.x;
    const int lane = tid & 31;
    const int warp = tid >> 5;      // 0..3
    const int wm = warp >> 1;       // 0..1
    const int wn = warp & 1;        // 0..1
    const int g  = lane >> 2;       // 0..7
    const int tg = lane & 3;        // 0..3

    // Slot pointers. At start of iter kt: p0->kt (compute), p1->kt+1 (prefetch
    // source), p2/p3 in flight, p4->kt-1 (consumed; refilled with kt+4).
    __half* pa[NST];
    __half* pb[NST];
    #pragma unroll
    for (int s = 0; s < NST; s++) {
        pa[s] = dsm + s * ASTAGE;
        pb[s] = dsm + NST * ASTAGE + s * BSTAGE;
    }

    // Loader: row = (tid>>2) + 32*i (i=0..3), 16B chunk = (tid&3)*8 halves
    const int lr  = tid >> 2;
    const int lc8 = (tid & 3) * 8;
    const __half* aptr = Ab + (long long)lr * lda + lc8;
    const __half* bptr = Bb + (long long)lr * ldb + lc8;

    // Fragment LDS offsets (halves) for this thread
    const int aoff_lo = (wm * 64 + g    ) * BK + tg * 8;   // mt=0 rows
    const int aoff_hi = (wm * 64 + g + 8) * BK + tg * 8;

    float acc[4][8][4];
    #pragma unroll
    for (int i = 0; i < 4; i++)
        #pragma unroll
        for (int j = 0; j < 8; j++)
            #pragma unroll
            for (int c = 0; c < 4; c++) acc[i][j][c] = 0.f;

    const int KT = K / BK;   // 32 or 128

    auto load = [&](const __half* ga, const __half* gb, __half* sa, __half* sb,
                    bool pred) {
        if (pred) {
            #pragma unroll
            for (int i = 0; i < 4; i++)
                cp16s(&sa[(lr + i * 32) * BK + lc8], ga + (long long)(i * 32) * lda);
            #pragma unroll
            for (int i = 0; i < 4; i++)
                cp16s(&sb[(lr + i * 32) * BK + lc8], gb + (long long)(i * 32) * ldb);
        }
        asm volatile("cp.async.commit_group;");
    };

    // Prologue: stages 0..3 into p0..p3
    #pragma unroll
    for (int s = 0; s < 4; s++) {
        load(aptr, bptr, pa[s], pb[s], true);
        aptr += BK;
        bptr += BK;
    }

    asm volatile("cp.async.wait_group 2;");  // stages 0,1 complete
    __syncthreads();

    // Preload B fragments and mt=0 A fragments for kt = 0 (stage 0)
    uint4 bb_cur[8];
    uint4 a0_cur[2];
    #pragma unroll
    for (int nt = 0; nt < 8; nt++)
        bb_cur[nt] = *(const uint4*)&pb[0][(wn * 64 + nt * 8 + g) * BK + tg * 8];
    a0_cur[0] = *(const uint4*)&pa[0][aoff_lo];
    a0_cur[1] = *(const uint4*)&pa[0][aoff_hi];

    for (int kt = 0; kt < KT; kt++) {
        // All but the 2 newest groups complete => stage kt+1 resident
        // (prefetch source for bb_nxt / a0_nxt).
        asm volatile("cp.async.wait_group 2;");
        __syncthreads();   // visibility + protects p4 (stage kt-1) overwrite

        load(aptr, bptr, pa[4], pb[4], kt + 4 < KT);
        aptr += BK;
        bptr += BK;

        const __half* as  = pa[0];
        const __half* asn = pa[1];
        const __half* bsn = pb[1];

        uint4 bb_nxt[8];
        uint4 a0_nxt[2];

        // ---- mt = 0: MMAs issue immediately from prefetched registers ----
        #pragma unroll
        for (int nt = 0; nt < 8; nt++)
            MMA_F16(acc[0][nt], a0_cur[0].x, a0_cur[1].x, a0_cur[0].y, a0_cur[1].y,
                    bb_cur[nt].x, bb_cur[nt].y);
        // Next-iteration B prefetch hides under mt0/mt1 MMAs
        #pragma unroll
        for (int nt = 0; nt < 8; nt++)
            bb_nxt[nt] = *(const uint4*)&bsn[(wn * 64 + nt * 8 + g) * BK + tg * 8];
        #pragma unroll
        for (int nt = 0; nt < 8; nt++)
            MMA_F16(acc[0][nt], a0_cur[0].z, a0_cur[1].z, a0_cur[0].w, a0_cur[1].w,
                    bb_cur[nt].z, bb_cur[nt].w);

        // ---- mt = 1..3: A loads hide under the previous block's MMAs ----
        #pragma unroll
        for (int mt = 1; mt < 4; mt++) {
            int r0 = wm * 64 + mt * 16;
            uint4 alo = *(const uint4*)&as[(r0 + g    ) * BK + tg * 8];
            uint4 ahi = *(const uint4*)&as[(r0 + g + 8) * BK + tg * 8];
            #pragma unroll
            for (int nt = 0; nt < 8; nt++)
                MMA_F16(acc[mt][nt], alo.x, ahi.x, alo.y, ahi.y,
                        bb_cur[nt].x, bb_cur[nt].y);
            if (mt == 3) {
                // Next-iteration mt=0 A prefetch (stage kt+1, published above)
                a0_nxt[0] = *(const uint4*)&asn[aoff_lo];
                a0_nxt[1] = *(const uint4*)&asn[aoff_hi];
            }
            #pragma unroll
            for (int nt = 0; nt < 8; nt++)
                MMA_F16(acc[mt][nt], alo.z, ahi.z, alo.w, ahi.w,
                        bb_cur[nt].z, bb_cur[nt].w);
        }

        #pragma unroll
        for (int nt = 0; nt < 8; nt++) bb_cur[nt] = bb_nxt[nt];
        a0_cur[0] = a0_nxt[0];
        a0_cur[1] = a0_nxt[1];

        // Rotate slots left: p0 <- p1 <- ... <- p4 <- p0
        __half* ta = pa[0]; __half* tb = pb[0];
        #pragma unroll
        for (int s = 0; s < NST - 1; s++) { pa[s] = pa[s + 1]; pb[s] = pb[s + 1]; }
        pa[NST - 1] = ta; pb[NST - 1] = tb;
    }

    // ---------------- Epilogue ----------------
    const int zq = (EPI == EPI_QKV) ? (int)blockIdx.z : 0;
    __half* Cq = nullptr;
    int ldq = ldc;
    if (EPI == EPI_QKV) {
        Cq = (zq == 0) ? g_Q : (zq == 1) ? g_K : g_Vt;
        ldq = (zq == 2) ? BT : DIM;
    }

    #pragma unroll
    for (int mt = 0; mt < 4; mt++) {
        int row0 = blockIdx.y * BM + wm * 64 + mt * 16 + g;   // within batch matrix
        float plo = 0.f, phi = 0.f;                            // EPI_EXP row partials
        float inv0 = 1.f, inv1 = 1.f;
        if (EPI == EPI_NORM) {
            const float* invp = aux + (long long)blockIdx.z * SEQ;
            inv0 = __ldg(&invp[row0]);
            inv1 = __ldg(&invp[row0 + 8]);
        }
        #pragma unroll
        for (int nt = 0; nt < 8; nt++) {
            int col0 = blockIdx.x * BN + wn * 64 + nt * 8 + 2 * tg;
            float v0 = acc[mt][nt][0] * alpha;
            float v1 = acc[mt][nt][1] * alpha;
            float v2 = acc[mt][nt][2] * alpha;
            float v3 = acc[mt][nt][3] * alpha;

            if (EPI == EPI_QKV) {
                if (zq < 2) {
                    __half2 h01 = __floats2half2_rn(v0, v1);
                    __half2 h23 = __floats2half2_rn(v2, v3);
                    *(__half2*)&Cq[(long long)(row0    ) * ldq + col0] = h01;
                    *(__half2*)&Cq[(long long)(row0 + 8) * ldq + col0] = h23;
                } else {
                    Cq[(long long)(col0    ) * ldq + row0    ] = __float2half_rn(v0);
                    Cq[(long long)(col0 + 1) * ldq + row0    ] = __float2half_rn(v1);
                    Cq[(long long)(col0    ) * ldq + row0 + 8] = __float2half_rn(v2);
                    Cq[(long long)(col0 + 1) * ldq + row0 + 8] = __float2half_rn(v3);
                }
            } else if (EPI == EPI_EXP) {
                __half* C = (__half*)Cv + (long long)blockIdx.z * sC;
                float e0 = __expf(fminf(v0, 11.f));
                float e1 = __expf(fminf(v1, 11.f));
                float e2 = __expf(fminf(v2, 11.f));
                float e3 = __expf(fminf(v3, 11.f));
                plo += e0 + e1; phi += e2 + e3;
                __half2 h01 = __floats2half2_rn(e0, e1);
                __half2 h23 = __floats2half2_rn(e2, e3);
                *(__half2*)&C[(long long)(row0    ) * ldc + col0] = h01;
                *(__half2*)&C[(long long)(row0 + 8) * ldc + col0] = h23;
            } else { // EPI_NORM
                float* C = (float*)Cv + (long long)blockIdx.z * sC;
                *(float2*)&C[(long long)(row0    ) * ldc + col0] =
                    make_float2(v0 * inv0, v1 * inv0);
                *(float2*)&C[(long long)(row0 + 8) * ldc + col0] =
                    make_float2(v2 * inv1, v3 * inv1);
            }
        }
        if (EPI == EPI_EXP) {
            // quad reduce across tg (lane bits 0,1), then leader stores partials.
            plo += __shfl_xor_sync(0xffffffffu, plo, 1);
            plo += __shfl_xor_sync(0xffffffffu, plo, 2);
            phi += __shfl_xor_sync(0xffffffffu, phi, 1);
            phi += __shfl_xor_sync(0xffffffffu, phi, 2);
            if (tg == 0) {
                long long slot = (long long)(blockIdx.x * 2 + wn) * BT
                               + (long long)blockIdx.z * SEQ;
                aux[slot + row0    ] = plo;
                aux[slot + row0 + 8] = phi;
            }
        }
    }
}

extern "C" void kernel_launch(void* const* d_in, const int* in_sizes, int n_in,
                              void* d_out, int out_size) {
    const float* x  = (const float*)d_in[0];
    const float* Wq = (const float*)d_in[1];
    const float* Wk = (const float*)d_in[2];
    const float* Wv = (const float*)d_in[3];
    float* out = (float*)d_out;

    __half *pX, *pQ, *pK, *pVt, *pP;
    float *pPsum, *pInv;
    cudaGetSymbolAddress((void**)&pX,  g_X);
    cudaGetSymbolAddress((void**)&pQ,  g_Q);
    cudaGetSymbolAddress((void**)&pK,  g_K);
    cudaGetSymbolAddress((void**)&pVt, g_Vt);
    cudaGetSymbolAddress((void**)&pP,  g_P);
    cudaGetSymbolAddress((void**)&pPsum, g_psum);
    cudaGetSymbolAddress((void**)&pInv,  g_inv);

    cudaFuncSetAttribute(gemm_f16<EPI_QKV >, cudaFuncAttributeMaxDynamicSharedMemorySize, SMEM_DYN);
    cudaFuncSetAttribute(gemm_f16<EPI_EXP >, cudaFuncAttributeMaxDynamicSharedMemorySize, SMEM_DYN);
    cudaFuncSetAttribute(gemm_f16<EPI_NORM>, cudaFuncAttributeMaxDynamicSharedMemorySize, SMEM_DYN);

    const long long nX = (long long)BT * DIM;
    const long long strideQK = (long long)SEQ * DIM;
    const long long strideS  = (long long)SEQ * SEQ;

    // Convert inputs to fp16 (x + all three weights in 2 launches)
    to_half_kernel<<<(unsigned)(nX / 4 / 256), 256>>>(x, pX, nX);
    w_to_half_kernel<<<3 * 1024, 256>>>(Wq, Wk, Wv);

    // Fused QKV projections: one launch, z selects weight + destination.
    dim3 gProj(DIM / BN, BT / BM, 3);
    gemm_f16<EPI_QKV><<<gProj, 128, SMEM_DYN>>>(pX, nullptr, nullptr, nullptr,
                                                DIM, DIM, DIM, 0, 0, 0, DIM, 1.0f);

    // Scores + exp fused: P_b = exp(Q_b K_b^T / 32), partial row sums to psum
    dim3 gS(SEQ / BN, SEQ / BM, BATCH);
    gemm_f16<EPI_EXP><<<gS, 128, SMEM_DYN>>>(pQ, pK, pP, pPsum, DIM, DIM, SEQ,
                                             strideQK, strideQK, strideS, DIM, 0.03125f);

    // Row sums -> reciprocals
    rowinv_kernel<<<BT / 256, 256>>>(pPsum, pInv);

    // Output: O_b = (P_b V_b) * inv_rowsum -> f32
    dim3 gO(DIM / BN, SEQ / BM, BATCH);
    gemm_f16<EPI_NORM><<<gO, 128, SMEM_DYN>>>(pP, pVt, out, pInv, SEQ, BT, DIM,
                                              strideS, (long long)SEQ, (long long)SEQ * DIM,
                                              SEQ, 1.0f);
}